// round 4
// baseline (speedup 1.0000x reference)
#include <cuda_runtime.h>
#include <cuda_bf16.h>
#include <cstdint>

// ---------------- problem constants ----------------
#define NXC 256
#define NYC 256
#define BC  8
#define DA  64
#define DR  64
#define CO  32

__device__ __constant__ float c_VX    = 0.3125f;          // 1/3.2
__device__ __constant__ float c_VY    = 0.3125f;
__device__ __constant__ float c_XOFF  = -39.84375f;       // VX/2 + X_MIN
__device__ __constant__ float c_YOFF  = -19.84375f;       // VY/2 + Y_MIN

// ---------------- scratch (device globals, zero-init at load) ----------------
__device__ float g_featA[60000 * DA];
__device__ float g_featR[80000 * DR];
__device__ int   g_ownerA[BC * NYC * NXC];
__device__ int   g_ownerR[BC * NYC * NXC];

// ============================================================================
// VFE: one block (64 threads) per pillar.
//   feats = mask * [voxels(C), xyz - mean(3), x - cx_off, y - cy_off]   (F = C+5)
//   h = relu(feats @ W + b);  out = max_p (h * mask)
// ============================================================================
template <int P, int C, int F>
__global__ __launch_bounds__(64) void vfe_kernel(
    const float* __restrict__ voxels, const int* __restrict__ coors,
    const int* __restrict__ nump, const float* __restrict__ W,
    const float* __restrict__ bias, float* __restrict__ out, int M)
{
    int i = blockIdx.x;
    if (i >= M) return;
    int d = threadIdx.x;  // output dim 0..63

    __shared__ float raw[P * C];
    __shared__ float feats[P * F];
    __shared__ float smean[3];

    const float* v = voxels + (size_t)i * (P * C);
    for (int k = d; k < P * C; k += 64) raw[k] = v[k];
    int np = nump[i];                 // guaranteed >= 1
    __syncthreads();

    if (d < 3) {
        float s = 0.f;
        for (int p = 0; p < np; ++p) s += raw[p * C + d];
        smean[d] = s / (float)np;
    }
    __syncthreads();

    int cx = coors[i * 3 + 2];
    int cy = coors[i * 3 + 1];
    float xoff = (float)cx * c_VX + c_XOFF;
    float yoff = (float)cy * c_VY + c_YOFF;

    for (int k = d; k < P * F; k += 64) {
        int p = k / F, c = k % F;
        float val;
        if (c < C)            val = raw[p * C + c];
        else if (c < C + 3)   val = raw[p * C + (c - C)] - smean[c - C];
        else if (c == C + 3)  val = raw[p * C + 0] - xoff;
        else                  val = raw[p * C + 1] - yoff;
        feats[k] = (p < np) ? val : 0.f;
    }
    __syncthreads();

    float w[F];
#pragma unroll
    for (int c = 0; c < F; ++c) w[c] = W[c * 64 + d];
    float bd = bias[d];

    float acc = 0.f;   // masked entries contribute 0; relu >= 0 so init 0 is exact
    for (int p = 0; p < np; ++p) {
        float dot = bd;
        const float* fp = &feats[p * F];
#pragma unroll
        for (int c = 0; c < F; ++c) dot = fmaf(fp[c], w[c], dot);
        float h = fmaxf(dot, 0.f);
        acc = fmaxf(acc, h);
    }
    out[(size_t)i * 64 + d] = acc;
}

// ============================================================================
// Owner resolution: last index wins (matches XLA .at[].set duplicate order).
// Stored as pillar_index + 1; zero-init means "empty". Idempotent across replays.
// ============================================================================
__global__ void owner_kernel(const int* __restrict__ coors, int M, int* __restrict__ owner)
{
    int i = blockIdx.x * blockDim.x + threadIdx.x;
    if (i >= M) return;
    int b = coors[i * 3 + 0];
    int y = coors[i * 3 + 1];
    int x = coors[i * 3 + 2];
    int cell = (b * NYC + y) * NXC + x;
    atomicMax(&owner[cell], i + 1);
}

// ============================================================================
// Output init: out[b,y,x,co] = conv_b[co]
// ============================================================================
__global__ void init_out_kernel(float* __restrict__ out, const float* __restrict__ cb, int n)
{
    int i = blockIdx.x * blockDim.x + threadIdx.x;
    if (i < n) out[i] = cb[i & (CO - 1)];
}

// ============================================================================
// Sparse scatter-conv.  grid.y = ky (0..2). Block: 256 threads (8 warps).
// Shared: weight slice w[ky][kx 0..2][ci 0..63][co 0..31] (24 KB) + per-warp
// feature staging (8 KB). Each warp processes 4 pillars at a time (weight-LDS
// amortized over 12 FMA).  lane == output channel co.
// Contribution: out[b, y0+1-ky, x0+1-kx, co] += sum_ci f[ci] * w[ky,kx,ci,co]
// ============================================================================
__global__ __launch_bounds__(256) void scatter_conv_kernel(
    const float* __restrict__ feats, const int* __restrict__ coors,
    const int* __restrict__ owner, const float* __restrict__ conv_w,
    int M, int ci_off, float* __restrict__ out)
{
    __shared__ float sw[3 * 64 * 32];    // [kx][ci][co]
    __shared__ float sf[8][4][64];       // [warp][pillar][ci]

    int ky  = blockIdx.y;
    int tid = threadIdx.x;

    for (int k = tid; k < 3 * 64 * 32; k += 256) {
        int kx = k >> 11, rem = k & 2047, ci = rem >> 5, co = rem & 31;
        sw[k] = conv_w[(((ky * 3 + kx) * 128) + ci_off + ci) * 32 + co];
    }
    __syncthreads();

    int warp = tid >> 5, lane = tid & 31;
    int gw = blockIdx.x * 8 + warp;
    int stride = gridDim.x * 8 * 4;

    for (int base = gw * 4; base < M; base += stride) {
        int  bb[4], yy[4], xx[4];
        bool valid[4];
#pragma unroll
        for (int t = 0; t < 4; ++t) {
            int i = base + t;
            bool v = false; int b = 0, y = 0, x = 0;
            float f0 = 0.f, f1 = 0.f;
            if (i < M) {
                b = coors[i * 3 + 0];
                y = coors[i * 3 + 1];
                x = coors[i * 3 + 2];
                int cell = (b * NYC + y) * NXC + x;
                v = (owner[cell] == i + 1);
                if (v) {
                    f0 = feats[(size_t)i * 64 + lane];
                    f1 = feats[(size_t)i * 64 + 32 + lane];
                }
            }
            valid[t] = v; bb[t] = b; yy[t] = y; xx[t] = x;
            sf[warp][t][lane]      = f0;
            sf[warp][t][lane + 32] = f1;
        }
        __syncwarp();

        float acc[4][3];
#pragma unroll
        for (int t = 0; t < 4; ++t) { acc[t][0] = 0.f; acc[t][1] = 0.f; acc[t][2] = 0.f; }

#pragma unroll 4
        for (int ci = 0; ci < 64; ++ci) {
            float w0 = sw[(0 * 64 + ci) * 32 + lane];
            float w1 = sw[(1 * 64 + ci) * 32 + lane];
            float w2 = sw[(2 * 64 + ci) * 32 + lane];
#pragma unroll
            for (int t = 0; t < 4; ++t) {
                float f = sf[warp][t][ci];
                acc[t][0] = fmaf(f, w0, acc[t][0]);
                acc[t][1] = fmaf(f, w1, acc[t][1]);
                acc[t][2] = fmaf(f, w2, acc[t][2]);
            }
        }

#pragma unroll
        for (int t = 0; t < 4; ++t) {
            if (!valid[t]) continue;
            int oy = yy[t] + 1 - ky;
            if (oy < 0 || oy >= NYC) continue;
            size_t rowbase = (((size_t)bb[t] * NYC + oy) * NXC);
#pragma unroll
            for (int kx = 0; kx < 3; ++kx) {
                int ox = xx[t] + 1 - kx;
                if (ox < 0 || ox >= NXC) continue;
                atomicAdd(&out[(rowbase + ox) * 32 + lane], acc[t][kx]);
            }
        }
        __syncwarp();
    }
}

// ============================================================================
// launch
// ============================================================================
extern "C" void kernel_launch(void* const* d_in, const int* in_sizes, int n_in,
                              void* d_out, int out_size)
{
    const float* voxels_agent = (const float*)d_in[0];
    const int*   coors_agent  = (const int*)  d_in[1];
    const int*   np_agent     = (const int*)  d_in[2];
    const float* voxels_rg    = (const float*)d_in[3];
    const int*   coors_rg     = (const int*)  d_in[4];
    const int*   np_rg        = (const int*)  d_in[5];
    const float* w_agent      = (const float*)d_in[6];
    const float* b_agent      = (const float*)d_in[7];
    const float* w_rg         = (const float*)d_in[8];
    const float* b_rg         = (const float*)d_in[9];
    const float* conv_w       = (const float*)d_in[10];
    const float* conv_b       = (const float*)d_in[11];

    int Ma = in_sizes[0] / (20 * 5);
    int Mr = in_sizes[3] / (32 * 3);
    float* out = (float*)d_out;

    float *featA, *featR;
    int   *ownerA, *ownerR;
    cudaGetSymbolAddress((void**)&featA,  g_featA);
    cudaGetSymbolAddress((void**)&featR,  g_featR);
    cudaGetSymbolAddress((void**)&ownerA, g_ownerA);
    cudaGetSymbolAddress((void**)&ownerR, g_ownerR);

    // 1) VFE encoders
    vfe_kernel<20, 5, 10><<<Ma, 64>>>(voxels_agent, coors_agent, np_agent,
                                      w_agent, b_agent, featA, Ma);
    vfe_kernel<32, 3, 8><<<Mr, 64>>>(voxels_rg, coors_rg, np_rg,
                                     w_rg, b_rg, featR, Mr);

    // 2) owner resolution (idempotent atomicMax)
    owner_kernel<<<(Ma + 255) / 256, 256>>>(coors_agent, Ma, ownerA);
    owner_kernel<<<(Mr + 255) / 256, 256>>>(coors_rg,    Mr, ownerR);

    // 3) output <- bias
    init_out_kernel<<<(out_size + 255) / 256, 256>>>(out, conv_b, out_size);

    // 4) sparse scatter-conv, agent channels [0,64) then rg channels [64,128)
    dim3 grid(296, 3);
    scatter_conv_kernel<<<grid, 256>>>(featA, coors_agent, ownerA, conv_w, Ma, 0,  out);
    scatter_conv_kernel<<<grid, 256>>>(featR, coors_rg,    ownerR, conv_w, Mr, 64, out);
}

// round 5
// speedup vs baseline: 1.3315x; 1.3315x over previous
#include <cuda_runtime.h>
#include <cuda_bf16.h>
#include <cstdint>

// ---------------- problem constants ----------------
#define NXC 256
#define NYC 256
#define BC  8
#define DA  64
#define DR  64
#define CO  32

__device__ __constant__ float c_VX    = 0.3125f;          // 1/3.2
__device__ __constant__ float c_VY    = 0.3125f;
__device__ __constant__ float c_XOFF  = -39.84375f;       // VX/2 + X_MIN
__device__ __constant__ float c_YOFF  = -19.84375f;       // VY/2 + Y_MIN

// ---------------- scratch (device globals, zero-init at load) ----------------
__device__ float g_featA[60000 * DA];
__device__ float g_featR[80000 * DR];
__device__ int   g_ownerA[BC * NYC * NXC];
__device__ int   g_ownerR[BC * NYC * NXC];

// ---------------- packed f32x2 helpers (FFMA2 via PTX, sm_100+) -------------
typedef unsigned long long ull;

__device__ __forceinline__ ull pack2(float lo, float hi) {
    ull r; asm("mov.b64 %0, {%1,%2};" : "=l"(r) : "f"(lo), "f"(hi)); return r;
}
__device__ __forceinline__ void fma2(ull& d, ull a, ull b) {
    asm("fma.rn.f32x2 %0, %1, %2, %3;" : "=l"(d) : "l"(a), "l"(b), "l"(d));
}
__device__ __forceinline__ float2 unpack2(ull v) {
    float2 r; asm("mov.b64 {%0,%1}, %2;" : "=f"(r.x), "=f"(r.y) : "l"(v)); return r;
}

// ============================================================================
// VFE: one block (64 threads) per pillar. Packed-pair dot product (F is even).
//   feats = mask * [voxels(C), xyz - mean(3), x - cx_off, y - cy_off]   (F=C+5... padded even)
//   h = relu(feats @ W + b);  out = max_p (h * mask)
// Also resolves scatter ownership (last index wins) via atomicMax.
// ============================================================================
template <int P, int C, int F>
__global__ __launch_bounds__(64) void vfe_kernel(
    const float* __restrict__ voxels, const int* __restrict__ coors,
    const int* __restrict__ nump, const float* __restrict__ W,
    const float* __restrict__ bias, float* __restrict__ out,
    int* __restrict__ owner, int M)
{
    static_assert((F & 1) == 0, "F must be even for packed pairs");
    int i = blockIdx.x;
    if (i >= M) return;
    int d = threadIdx.x;  // output dim 0..63

    __shared__ __align__(16) float raw[P * C];
    __shared__ __align__(16) float feats[P * F];
    __shared__ float smean[3];

    const float* v = voxels + (size_t)i * (P * C);
    for (int k = d; k < P * C; k += 64) raw[k] = v[k];
    int np = nump[i];                 // guaranteed >= 1
    __syncthreads();

    if (d < 3) {
        float s = 0.f;
        for (int p = 0; p < np; ++p) s += raw[p * C + d];
        smean[d] = s / (float)np;
    }
    __syncthreads();

    int cb = coors[i * 3 + 0];
    int cy = coors[i * 3 + 1];
    int cx = coors[i * 3 + 2];
    if (d == 0) {
        int cell = (cb * NYC + cy) * NXC + cx;
        atomicMax(&owner[cell], i + 1);   // idempotent across replays
    }
    float xoff = (float)cx * c_VX + c_XOFF;
    float yoff = (float)cy * c_VY + c_YOFF;

    for (int k = d; k < P * F; k += 64) {
        int p = k / F, c = k % F;
        float val;
        if (c < C)            val = raw[p * C + c];
        else if (c < C + 3)   val = raw[p * C + (c - C)] - smean[c - C];
        else if (c == C + 3)  val = raw[p * C + 0] - xoff;
        else                  val = raw[p * C + 1] - yoff;
        feats[k] = (p < np) ? val : 0.f;
    }
    __syncthreads();

    // packed weights: wp[c] = (W[2c][d], W[2c+1][d])
    ull wp[F / 2];
#pragma unroll
    for (int c = 0; c < F / 2; ++c)
        wp[c] = pack2(W[(2 * c) * 64 + d], W[(2 * c + 1) * 64 + d]);
    float bd = bias[d];

    float acc = 0.f;   // relu is folded: masked/neg entries can't beat 0
    for (int p = 0; p < np; ++p) {
        const ull* fp = reinterpret_cast<const ull*>(&feats[p * F]);
        ull d2 = 0;    // (0.0f, 0.0f)
#pragma unroll
        for (int c = 0; c < F / 2; ++c) fma2(d2, fp[c], wp[c]);
        float2 u = unpack2(d2);
        float dot = bd + u.x + u.y;
        acc = fmaxf(acc, dot);
    }
    out[(size_t)i * 64 + d] = acc;
}

// ============================================================================
// Output init: out[b,y,x,co] = conv_b[co]   (float4 vectorized)
// ============================================================================
__global__ void init_out_kernel(float4* __restrict__ out, const float* __restrict__ cb, int n4)
{
    int i = blockIdx.x * blockDim.x + threadIdx.x;
    if (i >= n4) return;
    int c = (i * 4) & (CO - 1);
    out[i] = make_float4(cb[c], cb[c + 1], cb[c + 2], cb[c + 3]);
}

// ============================================================================
// Sparse scatter-conv with packed FFMA2. grid.y = ky (0..2). 256 threads.
// Each warp batches T=8 pillars; accumulators packed over pillar pairs.
//   out[b, y0+1-ky, x0+1-kx, co] += sum_ci f[ci] * w[ky,kx,ci,co]
// sf layout: [warp][ci][t] with per-ci row padded to 10 floats:
//   - t-pair loads are 8B-aligned broadcast LDS.64 (conflict-free)
//   - staging STS across lanes (stride 10 floats) is at worst 2-way
// ============================================================================
#define SFP 10   // padded t-stride (even, stride/2 odd -> aligned + low conflict)

__global__ __launch_bounds__(256) void scatter_conv_kernel(
    const float* __restrict__ feats, const int* __restrict__ coors,
    const int* __restrict__ owner, const float* __restrict__ conv_w,
    int M, int ci_off, float* __restrict__ out)
{
    __shared__ __align__(16) float sw[3 * 64 * 32];     // [kx][ci][co]  24 KB
    __shared__ __align__(16) float sf[8 * 64 * SFP];    // [warp][ci][t] 20 KB

    int ky  = blockIdx.y;
    int tid = threadIdx.x;

    for (int k = tid; k < 3 * 64 * 32; k += 256) {
        int kx = k >> 11, rem = k & 2047, ci = rem >> 5, co = rem & 31;
        sw[k] = conv_w[(((ky * 3 + kx) * 128) + ci_off + ci) * 32 + co];
    }
    __syncthreads();

    int warp = tid >> 5, lane = tid & 31;
    float* sfw = sf + warp * (64 * SFP);
    int gw = blockIdx.x * 8 + warp;
    int stride = gridDim.x * 8 * 8;

    for (int base = gw * 8; base < M; base += stride) {
        int  bb[8], yy[8], xx[8];
        bool valid[8];
#pragma unroll
        for (int t = 0; t < 8; ++t) {
            int i = base + t;
            bool v = false; int b = 0, y = 0, x = 0;
            float f0 = 0.f, f1 = 0.f;
            if (i < M) {
                b = coors[i * 3 + 0];
                y = coors[i * 3 + 1];
                x = coors[i * 3 + 2];
                int cell = (b * NYC + y) * NXC + x;
                v = (owner[cell] == i + 1);
                f0 = feats[(size_t)i * 64 + lane];
                f1 = feats[(size_t)i * 64 + 32 + lane];
            }
            valid[t] = v; bb[t] = b; yy[t] = y; xx[t] = x;
            sfw[lane * SFP + t]        = f0;
            sfw[(lane + 32) * SFP + t] = f1;
        }
        __syncwarp();

        // packed accumulators: acc2[tp][kx] holds pillars (2tp, 2tp+1)
        ull acc2[4][3];
#pragma unroll
        for (int tp = 0; tp < 4; ++tp) { acc2[tp][0] = 0; acc2[tp][1] = 0; acc2[tp][2] = 0; }

#pragma unroll 8
        for (int ci = 0; ci < 64; ++ci) {
            float w0 = sw[(0 * 64 + ci) * 32 + lane];
            float w1 = sw[(1 * 64 + ci) * 32 + lane];
            float w2 = sw[(2 * 64 + ci) * 32 + lane];
            ull W0 = pack2(w0, w0), W1 = pack2(w1, w1), W2 = pack2(w2, w2);
            const float* frow = &sfw[ci * SFP];
#pragma unroll
            for (int tp = 0; tp < 4; ++tp) {
                ull f2 = *reinterpret_cast<const ull*>(frow + 2 * tp);  // broadcast LDS.64
                fma2(acc2[tp][0], f2, W0);
                fma2(acc2[tp][1], f2, W1);
                fma2(acc2[tp][2], f2, W2);
            }
        }

#pragma unroll
        for (int tp = 0; tp < 4; ++tp) {
            float2 a0 = unpack2(acc2[tp][0]);
            float2 a1 = unpack2(acc2[tp][1]);
            float2 a2 = unpack2(acc2[tp][2]);
            float av[2][3] = {{a0.x, a1.x, a2.x}, {a0.y, a1.y, a2.y}};
#pragma unroll
            for (int h = 0; h < 2; ++h) {
                int t = 2 * tp + h;
                if (!valid[t]) continue;
                int oy = yy[t] + 1 - ky;
                if (oy < 0 || oy >= NYC) continue;
                size_t rowbase = (((size_t)bb[t] * NYC + oy) * NXC);
#pragma unroll
                for (int kx = 0; kx < 3; ++kx) {
                    int ox = xx[t] + 1 - kx;
                    if (ox < 0 || ox >= NXC) continue;
                    atomicAdd(&out[(rowbase + ox) * 32 + lane], av[h][kx]);
                }
            }
        }
        __syncwarp();
    }
}

// ============================================================================
// launch
// ============================================================================
extern "C" void kernel_launch(void* const* d_in, const int* in_sizes, int n_in,
                              void* d_out, int out_size)
{
    const float* voxels_agent = (const float*)d_in[0];
    const int*   coors_agent  = (const int*)  d_in[1];
    const int*   np_agent     = (const int*)  d_in[2];
    const float* voxels_rg    = (const float*)d_in[3];
    const int*   coors_rg     = (const int*)  d_in[4];
    const int*   np_rg        = (const int*)  d_in[5];
    const float* w_agent      = (const float*)d_in[6];
    const float* b_agent      = (const float*)d_in[7];
    const float* w_rg         = (const float*)d_in[8];
    const float* b_rg         = (const float*)d_in[9];
    const float* conv_w       = (const float*)d_in[10];
    const float* conv_b       = (const float*)d_in[11];

    int Ma = in_sizes[0] / (20 * 5);
    int Mr = in_sizes[3] / (32 * 3);
    float* out = (float*)d_out;

    float *featA, *featR;
    int   *ownerA, *ownerR;
    cudaGetSymbolAddress((void**)&featA,  g_featA);
    cudaGetSymbolAddress((void**)&featR,  g_featR);
    cudaGetSymbolAddress((void**)&ownerA, g_ownerA);
    cudaGetSymbolAddress((void**)&ownerR, g_ownerR);

    // 1) VFE encoders (owner resolution fused in)
    vfe_kernel<20, 5, 10><<<Ma, 64>>>(voxels_agent, coors_agent, np_agent,
                                      w_agent, b_agent, featA, ownerA, Ma);
    vfe_kernel<32, 3, 8><<<Mr, 64>>>(voxels_rg, coors_rg, np_rg,
                                     w_rg, b_rg, featR, ownerR, Mr);

    // 2) output <- bias (float4)
    int n4 = out_size / 4;
    init_out_kernel<<<(n4 + 255) / 256, 256>>>((float4*)out, conv_b, n4);

    // 3) sparse scatter-conv, agent channels [0,64) then rg channels [64,128)
    dim3 grid(740, 3);
    scatter_conv_kernel<<<grid, 256>>>(featA, coors_agent, ownerA, conv_w, Ma, 0,  out);
    scatter_conv_kernel<<<grid, 256>>>(featR, coors_rg,    ownerR, conv_w, Mr, 64, out);
}

// round 6
// speedup vs baseline: 1.7700x; 1.3293x over previous
#include <cuda_runtime.h>
#include <cuda_bf16.h>
#include <cstdint>

// ---------------- problem constants ----------------
#define NXC 256
#define NYC 256
#define BC  8
#define CO  32

__device__ __constant__ float c_VX    = 0.3125f;          // 1/3.2
__device__ __constant__ float c_VY    = 0.3125f;
__device__ __constant__ float c_XOFF  = -39.84375f;       // VX/2 + X_MIN
__device__ __constant__ float c_YOFF  = -19.84375f;       // VY/2 + Y_MIN

// ---------------- scratch (device globals, zero-init at load) ----------------
__device__ float g_featA[60000 * 64];
__device__ float g_featR[80000 * 64];
__device__ int   g_ownerA[BC * NYC * NXC];
__device__ int   g_ownerR[BC * NYC * NXC];

// ---------------- packed f32x2 helpers (FFMA2 via PTX, sm_100+) -------------
typedef unsigned long long ull;

__device__ __forceinline__ ull pack2(float lo, float hi) {
    ull r; asm("mov.b64 %0, {%1,%2};" : "=l"(r) : "f"(lo), "f"(hi)); return r;
}
__device__ __forceinline__ void fma2(ull& d, ull a, ull b) {
    asm("fma.rn.f32x2 %0, %1, %2, %3;" : "=l"(d) : "l"(a), "l"(b), "l"(d));
}
__device__ __forceinline__ float2 unpack2(ull v) {
    float2 r; asm("mov.b64 {%0,%1}, %2;" : "=f"(r.x), "=f"(r.y) : "l"(v)); return r;
}
__device__ __forceinline__ void red_add_v2(float* p, float x, float y) {
    asm volatile("red.global.add.v2.f32 [%0], {%1,%2};" :: "l"(p), "f"(x), "f"(y) : "memory");
}

// ============================================================================
// VFE body (algebraically folded). One block (64 threads) per pillar.
// dot_p = sum_{c<C} v_c * we_c + K   where
//   we0 = w0 + w_C   + w_{C+3},  we1 = w1 + w_{C+1} + w_{C+4},  we2 = w2 + w_{C+2}
//   K = b - mx*w_C - my*w_{C+1} - mz*w_{C+2} - xo*w_{C+3} - yo*w_{C+4}
// out = max(0, max_{p<np} dot_p)   (relu folded; masked rows contribute 0)
// Also resolves scatter ownership (last index wins) via idempotent atomicMax.
// ============================================================================
template <int P, int C>
__device__ __forceinline__ void vfe_body(
    const float* __restrict__ voxels, const int* __restrict__ coors,
    const int* __restrict__ nump, const float* __restrict__ W,
    const float* __restrict__ bias, float* __restrict__ outf,
    int* __restrict__ owner, int i, float* raw, float* smean)
{
    int d = threadIdx.x;
    const float* v = voxels + (size_t)i * (P * C);
    for (int k = d; k < P * C; k += 64) raw[k] = v[k];
    int np = nump[i];                 // >= 1
    __syncthreads();

    if (d < 3) {
        float s = 0.f;
        for (int p = 0; p < np; ++p) s += raw[p * C + d];
        smean[d] = s / (float)np;
    }
    __syncthreads();

    int cb = coors[3 * i], cy = coors[3 * i + 1], cx = coors[3 * i + 2];
    if (d == 0) atomicMax(&owner[(cb * NYC + cy) * NXC + cx], i + 1);
    float xo = (float)cx * c_VX + c_XOFF;
    float yo = (float)cy * c_VY + c_YOFF;

    float wC0 = W[(C + 0) * 64 + d], wC1 = W[(C + 1) * 64 + d], wC2 = W[(C + 2) * 64 + d];
    float wC3 = W[(C + 3) * 64 + d], wC4 = W[(C + 4) * 64 + d];
    float we[C];
#pragma unroll
    for (int c = 0; c < C; ++c) we[c] = W[c * 64 + d];
    we[0] += wC0 + wC3;
    we[1] += wC1 + wC4;
    we[2] += wC2;
    float K = bias[d] - smean[0] * wC0 - smean[1] * wC1 - smean[2] * wC2
                       - xo * wC3 - yo * wC4;

    float acc0 = 0.f, acc1 = 0.f;
    int p = 0;
    for (; p + 2 <= np; p += 2) {
        float d0 = K, d1 = K;
        const float* r0 = &raw[p * C];
#pragma unroll
        for (int c = 0; c < C; ++c) {
            d0 = fmaf(r0[c],     we[c], d0);
            d1 = fmaf(r0[C + c], we[c], d1);
        }
        acc0 = fmaxf(acc0, d0); acc1 = fmaxf(acc1, d1);
    }
    if (p < np) {
        float d0 = K;
        const float* r0 = &raw[p * C];
#pragma unroll
        for (int c = 0; c < C; ++c) d0 = fmaf(r0[c], we[c], d0);
        acc0 = fmaxf(acc0, d0);
    }
    outf[(size_t)i * 64 + d] = fmaxf(acc0, acc1);
}

// ============================================================================
// Fused prep kernel: [init blocks | VFE agent | VFE rg]
// ============================================================================
#define INITB 4096

__global__ __launch_bounds__(64) void prep_kernel(
    const float* voxA, const int* cA, const int* npA, const float* wA, const float* bA,
    const float* voxR, const int* cR, const int* npR, const float* wR, const float* bR,
    float* featA, float* featR, int* ownerA, int* ownerR, int Ma, int Mr,
    float4* out4, const float* __restrict__ cb, int n4)
{
    __shared__ __align__(16) float raw[160];
    __shared__ float smean[3];

    int bid = blockIdx.x;
    if (bid < INITB) {
        for (int i = bid * 64 + threadIdx.x; i < n4; i += INITB * 64) {
            int c = (i * 4) & (CO - 1);
            out4[i] = make_float4(cb[c], cb[c + 1], cb[c + 2], cb[c + 3]);
        }
    } else if (bid < INITB + Ma) {
        vfe_body<20, 5>(voxA, cA, npA, wA, bA, featA, ownerA, bid - INITB, raw, smean);
    } else {
        vfe_body<32, 3>(voxR, cR, npR, wR, bR, featR, ownerR, bid - INITB - Ma, raw, smean);
    }
}

// ============================================================================
// Fused sparse scatter-conv, all 9 taps in one pass, co-pair packed FFMA2.
// Block = 256 threads (8 warps), T=8 pillars per warp.
// Lane: c2 = 2*(lane&15) -> co pair; h = lane>>4 -> pillar parity.
// acc[tp][tap] packs (co=c2, co=c2+1) for pillar t = 2*tp + h.
// Weights load as natural LDS.64 pairs (no dup ALU); each feature LDS feeds
// 9 FFMA2. Epilogue: red.global.add.v2.f32 (one warp instr covers 2 pillars).
// smem: sw[9][64][32] (72KB) + sf[8 warps][64 ci][stride 9] (18KB) = 90KB.
// ============================================================================
#define CONV_SMEM (9 * 64 * 32 * 4 + 8 * 64 * 9 * 4)

__global__ __launch_bounds__(256, 2) void conv_kernel(
    const float* __restrict__ fA, const int* __restrict__ cA, const int* __restrict__ oA, int Ma,
    const float* __restrict__ fR, const int* __restrict__ cR, const int* __restrict__ oR, int Mr,
    const float* __restrict__ conv_w, float* __restrict__ out, int Ga, int Gr)
{
    extern __shared__ __align__(16) float smem[];
    float* sw = smem;                 // [tap][ci][co]
    float* sf = smem + 9 * 64 * 32;   // [warp][ci][t(stride 9)]

    bool isA = (int)blockIdx.x < Ga;
    const float* feats = isA ? fA : fR;
    const int*   coors = isA ? cA : cR;
    const int*   owner = isA ? oA : oR;
    int M      = isA ? Ma : Mr;
    int ci_off = isA ? 0 : 64;
    int nblk   = isA ? Ga : Gr;
    int blk    = isA ? blockIdx.x : blockIdx.x - Ga;

    int tid = threadIdx.x;
    for (int k = tid; k < 9 * 64 * 32; k += 256) {
        int tap = k >> 11, rem = k & 2047;              // rem = ci*32+co
        sw[k] = conv_w[(tap * 128 + ci_off + (rem >> 5)) * 32 + (rem & 31)];
    }
    __syncthreads();

    int warp = tid >> 5, lane = tid & 31;
    int h = lane >> 4;                 // pillar parity this lane owns
    int c2 = (lane & 15) * 2;          // co pair
    float* sfw = sf + warp * (64 * 9);

    int stride = nblk * 8 * 8;         // blocks * warps * T
    for (int base = (blk * 8 + warp) * 8; base < M; base += stride) {
        int myb[4], myy[4], myx[4]; bool myv[4];
#pragma unroll
        for (int t = 0; t < 8; ++t) {
            int i = base + t;
            float f0 = 0.f, f1 = 0.f; int b = 0, y = 0, x = 0; bool v = false;
            if (i < M) {
                b = coors[3 * i]; y = coors[3 * i + 1]; x = coors[3 * i + 2];
                v = (owner[(b * NYC + y) * NXC + x] == i + 1);
                f0 = feats[(size_t)i * 64 + lane];
                f1 = feats[(size_t)i * 64 + 32 + lane];
            }
            sfw[lane * 9 + t]        = f0;   // stride 9 -> conflict-free
            sfw[(lane + 32) * 9 + t] = f1;
            if ((t & 1) == h) {
                int tp = t >> 1;
                myb[tp] = b; myy[tp] = y; myx[tp] = x; myv[tp] = v;
            }
        }
        __syncwarp();

        ull acc[4][9];
#pragma unroll
        for (int tp = 0; tp < 4; ++tp)
#pragma unroll
            for (int k = 0; k < 9; ++k) acc[tp][k] = 0ULL;

#pragma unroll 4
        for (int ci = 0; ci < 64; ++ci) {
            ull f2[4];
#pragma unroll
            for (int tp = 0; tp < 4; ++tp) {
                float fv = sfw[ci * 9 + 2 * tp + h];
                f2[tp] = pack2(fv, fv);
            }
            const float* wrow = sw + ci * 32 + c2;
#pragma unroll
            for (int tap = 0; tap < 9; ++tap) {
                ull w2 = *reinterpret_cast<const ull*>(wrow + tap * 2048);  // LDS.64 pair
#pragma unroll
                for (int tp = 0; tp < 4; ++tp) fma2(acc[tp][tap], f2[tp], w2);
            }
        }

#pragma unroll
        for (int tp = 0; tp < 4; ++tp) {
            if (!myv[tp]) continue;
#pragma unroll
            for (int ky = 0; ky < 3; ++ky) {
                int oy = myy[tp] + 1 - ky;
                if ((unsigned)oy >= NYC) continue;
                size_t rb = ((size_t)myb[tp] * NYC + oy) * NXC;
#pragma unroll
                for (int kx = 0; kx < 3; ++kx) {
                    int ox = myx[tp] + 1 - kx;
                    if ((unsigned)ox >= NXC) continue;
                    float2 v2 = unpack2(acc[tp][ky * 3 + kx]);
                    red_add_v2(out + (rb + ox) * 32 + c2, v2.x, v2.y);
                }
            }
        }
        __syncwarp();
    }
}

// ============================================================================
// launch
// ============================================================================
extern "C" void kernel_launch(void* const* d_in, const int* in_sizes, int n_in,
                              void* d_out, int out_size)
{
    const float* voxels_agent = (const float*)d_in[0];
    const int*   coors_agent  = (const int*)  d_in[1];
    const int*   np_agent     = (const int*)  d_in[2];
    const float* voxels_rg    = (const float*)d_in[3];
    const int*   coors_rg     = (const int*)  d_in[4];
    const int*   np_rg        = (const int*)  d_in[5];
    const float* w_agent      = (const float*)d_in[6];
    const float* b_agent      = (const float*)d_in[7];
    const float* w_rg         = (const float*)d_in[8];
    const float* b_rg         = (const float*)d_in[9];
    const float* conv_w       = (const float*)d_in[10];
    const float* conv_b       = (const float*)d_in[11];

    int Ma = in_sizes[0] / (20 * 5);
    int Mr = in_sizes[3] / (32 * 3);
    float* out = (float*)d_out;

    float *featA, *featR;
    int   *ownerA, *ownerR;
    cudaGetSymbolAddress((void**)&featA,  g_featA);
    cudaGetSymbolAddress((void**)&featR,  g_featR);
    cudaGetSymbolAddress((void**)&ownerA, g_ownerA);
    cudaGetSymbolAddress((void**)&ownerR, g_ownerR);

    // 1) fused init + VFE (agent, rg) + owner resolution
    int n4 = out_size / 4;
    prep_kernel<<<INITB + Ma + Mr, 64>>>(
        voxels_agent, coors_agent, np_agent, w_agent, b_agent,
        voxels_rg, coors_rg, np_rg, w_rg, b_rg,
        featA, featR, ownerA, ownerR, Ma, Mr,
        (float4*)out, conv_b, n4);

    // 2) fused sparse scatter-conv (both sets, all 9 taps)
    static bool attr_set = false;
    cudaFuncSetAttribute(conv_kernel, cudaFuncAttributeMaxDynamicSharedMemorySize, CONV_SMEM);
    (void)attr_set;
    int total = Ma + Mr;
    int G = 296;                               // 2 CTAs/SM on 148 SMs
    int Ga = (int)((long long)G * Ma / total);
    if (Ga < 1) Ga = 1; if (Ga > G - 1) Ga = G - 1;
    int Gr = G - Ga;
    conv_kernel<<<G, 256, CONV_SMEM>>>(featA, coors_agent, ownerA, Ma,
                                       featR, coors_rg,    ownerR, Mr,
                                       conv_w, out, Ga, Gr);
}